// round 7
// baseline (speedup 1.0000x reference)
#include <cuda_runtime.h>
#include <cuda_bf16.h>
#include <mma.h>
#include <cstddef>

using namespace nvcuda;

#define BATCH 256
#define HID   512
#define K2    1024          // fused K: [H | E] @ [Wl ; Wr]
#define KC    128           // K-chunk per group per iteration
#define NCH   4             // 512 / KC  (each group owns half of K2)

// scratch (allocation-free per harness rules)
__device__ float         g_H[2][BATCH][HID];
__device__ __nv_bfloat16 g_Whi[K2][HID];
__device__ __nv_bfloat16 g_Wlo[K2][HID];

// tokens may be int32 (jax default) or int64. tokens[0][1] is a real token
// >= 3, so a zero second word means little-endian int64.
__device__ __forceinline__ int load_tok(const int* tokens, long long idx)
{
    if (tokens[1] == 0) return (int)((const long long*)tokens)[idx];
    return tokens[idx];
}

__device__ __forceinline__ void split_bf16(float x, __nv_bfloat16& hi, __nv_bfloat16& lo)
{
    hi = __float2bfloat16(x);
    lo = __float2bfloat16(x - __bfloat162float(hi));
}

// Split [Wl ; Wr] into hi/lo bf16 planes (idempotent, runs in-graph).
__global__ void prep_kernel(const float* __restrict__ Wl,
                            const float* __restrict__ Wr)
{
    int e = (blockIdx.x * blockDim.x + threadIdx.x) * 4;
    if (e >= K2 * HID) return;
    int row = e >> 9;          // /512
    int col = e & (HID - 1);
    const float* src = (row < HID) ? (Wl + (size_t)row * HID + col)
                                   : (Wr + (size_t)(row - HID) * HID + col);
    float4 v = *(const float4*)src;
    float xs[4] = {v.x, v.y, v.z, v.w};
    #pragma unroll
    for (int j = 0; j < 4; ++j) {
        __nv_bfloat16 h, l;
        split_bf16(xs[j], h, l);
        g_Whi[row][col + j] = h;
        g_Wlo[row][col + j] = l;
    }
}

// h0[b][:] = emb[tok0[b]][:]
__global__ void init_kernel(const int* __restrict__ tokens,
                            const float* __restrict__ emb)
{
    int b = blockIdx.x;
    int tok = load_tok(tokens, b);
    const float4* s = (const float4*)(emb + (size_t)tok * HID);
    float4* d = (float4*)(&g_H[0][b][0]);
    d[threadIdx.x] = s[threadIdx.x];
}

// One chain step: Hdst = tanh(Hsrc @ Wl + emb[tok_row] @ Wr + bias)
// Block = 32x32 output tile, 8 warps in 2 K-groups of 4:
//   group 0 (warps 0-3): K rows 0..511    (Hsrc @ Wl)
//   group 1 (warps 4-7): K rows 512..1023 (emb-gather @ Wr)
// Each warp owns one 16x16 output quadrant for its group; 3-term bf16-split
// wmma (hi*hi + hi*lo + lo*hi) gives ~fp32 accuracy on tensor cores.
// A chunks staged+split in smem with register prefetch; W hi/lo fragments
// loaded straight from the precomputed global planes (L1-resident reuse).
__global__ void __launch_bounds__(256, 1)
step_kernel(const int* __restrict__ tokens,
            long long rowoff,
            const float* __restrict__ emb,
            const float* __restrict__ bias,
            const float* __restrict__ Hsrc,
            float* __restrict__ Hdst)
{
    __shared__ __align__(16) union {
        struct {
            __nv_bfloat16 hi[2][32][KC];
            __nv_bfloat16 lo[2][32][KC];
        } st;
        float red[8][16][16];
    } sm;
    __shared__ int stok[32];

    const int tid  = threadIdx.x;
    const int w    = tid >> 5;
    const int g    = w >> 2;        // compute K-group
    const int q    = w & 3;
    const int mi   = q >> 1;        // quadrant row
    const int ni   = q & 1;         // quadrant col
    const int rb   = blockIdx.y * 32;
    const int cb   = blockIdx.x * 32;

    if (tid < 32) stok[tid] = load_tok(tokens, rowoff + rb + tid);
    __syncthreads();

    // staging roles: 128 threads per group, 32 consecutive floats each
    const int sg   = tid >> 7;      // staging group == compute group
    const int t    = tid & 127;
    const int srow = t >> 2;
    const int sq   = t & 3;
    const float* Abase = (sg == 0)
        ? (Hsrc + (size_t)(rb + srow) * HID)
        : (emb  + (size_t)stok[srow] * HID);

    wmma::fragment<wmma::accumulator, 16, 16, 16, float> acc;
    wmma::fill_fragment(acc, 0.0f);

    // prefetch chunk 0
    float4 pre[8];
    {
        const float* p = Abase + sq * 32;
        #pragma unroll
        for (int i = 0; i < 8; ++i) pre[i] = *(const float4*)(p + i * 4);
    }

    #pragma unroll 1
    for (int c = 0; c < NCH; ++c) {
        // split + stage A chunk
        __nv_bfloat16* hp = &sm.st.hi[sg][srow][sq * 32];
        __nv_bfloat16* lp = &sm.st.lo[sg][srow][sq * 32];
        #pragma unroll
        for (int i = 0; i < 8; ++i) {
            float xs[4] = {pre[i].x, pre[i].y, pre[i].z, pre[i].w};
            #pragma unroll
            for (int j = 0; j < 4; ++j) {
                __nv_bfloat16 h, l;
                split_bf16(xs[j], h, l);
                hp[i * 4 + j] = h;
                lp[i * 4 + j] = l;
            }
        }
        __syncthreads();

        if (c + 1 < NCH) {      // prefetch next chunk during compute
            const float* p = Abase + (c + 1) * KC + sq * 32;
            #pragma unroll
            for (int i = 0; i < 8; ++i) pre[i] = *(const float4*)(p + i * 4);
        }

        const int kglob = g * 512 + c * KC;
        #pragma unroll
        for (int kk = 0; kk < KC / 16; ++kk) {
            wmma::fragment<wmma::matrix_a, 16, 16, 16, __nv_bfloat16, wmma::row_major> ah, al;
            wmma::fragment<wmma::matrix_b, 16, 16, 16, __nv_bfloat16, wmma::row_major> bh, bl;
            wmma::load_matrix_sync(ah, &sm.st.hi[g][mi * 16][kk * 16], KC);
            wmma::load_matrix_sync(al, &sm.st.lo[g][mi * 16][kk * 16], KC);
            wmma::load_matrix_sync(bh, &g_Whi[kglob + kk * 16][cb + ni * 16], HID);
            wmma::load_matrix_sync(bl, &g_Wlo[kglob + kk * 16][cb + ni * 16], HID);
            wmma::mma_sync(acc, ah, bh, acc);
            wmma::mma_sync(acc, ah, bl, acc);
            wmma::mma_sync(acc, al, bh, acc);
        }
        __syncthreads();
    }

    // combine group partials through smem (stage region is dead now)
    wmma::store_matrix_sync(&sm.red[w][0][0], acc, 16, wmma::mem_row_major);
    __syncthreads();

    // 256 threads x 4 outputs: bias + tanh + fp32 store
    const int r   = tid >> 3;            // 0..31
    const int cc0 = (tid & 7) * 4;       // 0..28, stays inside one quadrant
    const int q2  = (r >> 4) * 2 + (cc0 >> 4);
    const int rr  = r & 15;
    float v[4];
    #pragma unroll
    for (int j = 0; j < 4; ++j) {
        int cc = cc0 + j;
        float x = sm.red[q2][rr][cc & 15] + sm.red[4 + q2][rr][cc & 15]
                + bias[cb + cc];
        v[j] = tanhf(x);
    }
    *(float4*)&Hdst[(size_t)(rb + r) * HID + cb + cc0] =
        make_float4(v[0], v[1], v[2], v[3]);
}

extern "C" void kernel_launch(void* const* d_in, const int* in_sizes, int n_in,
                              void* d_out, int out_size)
{
    const int*   tokens = (const int*)  d_in[0];   // [511, 256]
    const float* emb    = (const float*)d_in[1];   // [32000, 512]
    const float* Wl     = (const float*)d_in[2];   // [512, 512]
    const float* Wr     = (const float*)d_in[3];   // [512, 512]
    const float* bias   = (const float*)d_in[4];   // [512]
    float* out = (float*)d_out;                    // [256, 512]

    void* hp = nullptr;
    cudaGetSymbolAddress(&hp, g_H);
    float* H0 = (float*)hp;
    float* H1 = H0 + BATCH * HID;

    const int T      = in_sizes[0] / BATCH;  // 511
    const int nsteps = (T - 1) / 2;          // 255 reduce steps

    prep_kernel<<<(K2 * HID / 4 + 255) / 256, 256>>>(Wl, Wr);
    init_kernel<<<BATCH, HID / 4>>>(tokens, emb);

    dim3 grid(HID / 32, BATCH / 32);         // (16, 8) = 128 blocks
    for (int i = 1; i <= nsteps; ++i) {
        const float* src = (i & 1) ? H0 : H1;
        float* dst = (i == nsteps) ? out : ((i & 1) ? H1 : H0);
        long long rowoff = (long long)(2 * i - 1) * BATCH;
        step_kernel<<<grid, 256>>>(tokens, rowoff, emb, bias, src, dst);
    }
}

// round 8
// speedup vs baseline: 2.1263x; 2.1263x over previous
#include <cuda_runtime.h>
#include <cuda_bf16.h>
#include <mma.h>
#include <cstddef>

using namespace nvcuda;

#define BATCH 256
#define HID   512
#define NBLK  128          // 16 col-tiles x 8 row-tiles, all co-resident (<=148 SMs)
#define KC    128          // K-chunk per group per iteration
#define NCH   4            // 512 / KC (each warp-group owns half of fused K=1024)
#define WPAD  40           // 32 + 8 pad -> 80B rows, conflict-free ldmatrix
#define APAD  136          // 128 + 8 pad -> 272B rows, conflict-free ldmatrix

// scratch (allocation-free per harness rules)
__device__ float    g_H[2][BATCH][HID];
__device__ unsigned g_cnt;              // monotonic grid-barrier counter

struct SMem {
    __nv_bfloat16 Whi[1024][WPAD];      // 80KB   this block's W column slice, hi plane
    __nv_bfloat16 Wlo[1024][WPAD];      // 80KB   lo plane
    union {
        struct { __nv_bfloat16 hi[2][32][APAD];
                 __nv_bfloat16 lo[2][32][APAD]; } a;   // 34KB A staging
        float red[8][16][16];                          // 8KB partial reduction
    } u;
    int stok[32];
};

// tokens may be int32 (jax default) or int64. tokens[0][1] is a real token
// >= 3, so a zero second 32-bit word means little-endian int64.
__device__ __forceinline__ int load_tok(const int* tokens, long long idx)
{
    if (tokens[1] == 0) return (int)((const long long*)tokens)[idx];
    return tokens[idx];
}

__device__ __forceinline__ void split_bf16(float x, __nv_bfloat16& hi, __nv_bfloat16& lo)
{
    hi = __float2bfloat16(x);
    lo = __float2bfloat16(x - __bfloat162float(hi));
}

// h0[b][:] = emb[tok0[b]][:] ; also resets the grid-barrier counter each replay
__global__ void init_kernel(const int* __restrict__ tokens,
                            const float* __restrict__ emb)
{
    if (blockIdx.x == 0 && threadIdx.x == 0) g_cnt = 0u;
    int b = blockIdx.x;
    int tok = load_tok(tokens, b);
    const float4* s = (const float4*)(emb + (size_t)tok * HID);
    float4* d = (float4*)(&g_H[0][b][0]);
    d[threadIdx.x] = s[threadIdx.x];
}

// Persistent chain kernel: all 255 reduce steps in one launch.
// Block = 32x32 output tile. 8 warps in 2 K-groups of 4:
//   group 0 (warps 0-3): K 0..511    = Hsrc @ Wl
//   group 1 (warps 4-7): K 512..1023 = emb-gather @ Wr
// W slice split to bf16 hi/lo ONCE into smem; every step reuses it.
// Steps separated by a monotonic-counter grid barrier with gpu-scope fences
// (the fence's L1 invalidate also keeps the ping-pong H buffers coherent).
__global__ void __launch_bounds__(256, 1)
chain_kernel(const int* __restrict__ tokens,
             const float* __restrict__ emb,
             const float* __restrict__ Wl,
             const float* __restrict__ Wr,
             const float* __restrict__ bias,
             float* __restrict__ out,
             int nsteps)
{
    extern __shared__ char smem_raw[];
    SMem& sm = *reinterpret_cast<SMem*>(smem_raw);

    const int tid = threadIdx.x;
    const int w   = tid >> 5;
    const int g   = w >> 2;         // compute K-group
    const int q   = w & 3;
    const int mi  = q >> 1;         // 16x16 quadrant row
    const int ni  = q & 1;          // quadrant col
    const int cb  = (blockIdx.x & 15) * 32;
    const int rb  = (blockIdx.x >> 4) * 32;

    // ---- one-time: load + split this block's W column slice into smem ----
    {
        const int row0 = tid >> 3;
        const int cq   = (tid & 7) * 4;
        for (int it = 0; it < 32; ++it) {
            int row = it * 32 + row0;                  // 0..1023 over [Wl ; Wr]
            const float* src = (row < HID)
                ? (Wl + (size_t)row * HID + cb + cq)
                : (Wr + (size_t)(row - HID) * HID + cb + cq);
            float4 v = *(const float4*)src;
            float xs[4] = {v.x, v.y, v.z, v.w};
            #pragma unroll
            for (int j = 0; j < 4; ++j) {
                __nv_bfloat16 h, l;
                split_bf16(xs[j], h, l);
                sm.Whi[row][cq + j] = h;
                sm.Wlo[row][cq + j] = l;
            }
        }
    }
    __syncthreads();

    // staging roles: 128 threads per group, 32 consecutive floats each
    const int sg   = tid >> 7;      // staging group == compute group
    const int t    = tid & 127;
    const int srow = t >> 2;
    const int sq   = t & 3;

    for (int s = 1; s <= nsteps; ++s) {
        const float* Hsrc = &g_H[(s - 1) & 1][0][0];
        float* Hdst = (s == nsteps) ? out : &g_H[s & 1][0][0];

        if (tid < 32)
            sm.stok[tid] = load_tok(tokens, (long long)(2 * s - 1) * BATCH + rb + tid);
        __syncthreads();

        const float* Abase = (sg == 0)
            ? (Hsrc + (size_t)(rb + srow) * HID)
            : (emb  + (size_t)sm.stok[srow] * HID);

        wmma::fragment<wmma::accumulator, 16, 16, 16, float> acc;
        wmma::fill_fragment(acc, 0.0f);

        // prefetch chunk 0
        float4 pre[8];
        {
            const float* p = Abase + sq * 32;
            #pragma unroll
            for (int i = 0; i < 8; ++i) pre[i] = *(const float4*)(p + i * 4);
        }

        #pragma unroll 1
        for (int c = 0; c < NCH; ++c) {
            // split + stage A chunk
            __nv_bfloat16* hp = &sm.u.a.hi[sg][srow][sq * 32];
            __nv_bfloat16* lp = &sm.u.a.lo[sg][srow][sq * 32];
            #pragma unroll
            for (int i = 0; i < 8; ++i) {
                float xs[4] = {pre[i].x, pre[i].y, pre[i].z, pre[i].w};
                #pragma unroll
                for (int j = 0; j < 4; ++j) {
                    __nv_bfloat16 h, l;
                    split_bf16(xs[j], h, l);
                    hp[i * 4 + j] = h;
                    lp[i * 4 + j] = l;
                }
            }
            __syncthreads();

            if (c + 1 < NCH) {      // prefetch next chunk during compute
                const float* p = Abase + (c + 1) * KC + sq * 32;
                #pragma unroll
                for (int i = 0; i < 8; ++i) pre[i] = *(const float4*)(p + i * 4);
            }

            const int kglob = g * 512 + c * KC;
            #pragma unroll
            for (int kk = 0; kk < KC / 16; ++kk) {
                wmma::fragment<wmma::matrix_a, 16, 16, 16, __nv_bfloat16, wmma::row_major> ah, al;
                wmma::fragment<wmma::matrix_b, 16, 16, 16, __nv_bfloat16, wmma::row_major> bh, bl;
                wmma::load_matrix_sync(ah, &sm.u.a.hi[g][mi * 16][kk * 16], APAD);
                wmma::load_matrix_sync(al, &sm.u.a.lo[g][mi * 16][kk * 16], APAD);
                wmma::load_matrix_sync(bh, &sm.Whi[kglob + kk * 16][ni * 16], WPAD);
                wmma::load_matrix_sync(bl, &sm.Wlo[kglob + kk * 16][ni * 16], WPAD);
                wmma::mma_sync(acc, ah, bh, acc);
                wmma::mma_sync(acc, ah, bl, acc);
                wmma::mma_sync(acc, al, bh, acc);
            }
            __syncthreads();
        }

        // combine the two group partials through smem (stage region is dead)
        wmma::store_matrix_sync(&sm.u.red[w][0][0], acc, 16, wmma::mem_row_major);
        __syncthreads();

        // 256 threads x 4 outputs: bias + tanh + fp32 store
        {
            const int r   = tid >> 3;
            const int cc0 = (tid & 7) * 4;       // stays inside one quadrant
            const int q2  = (r >> 4) * 2 + (cc0 >> 4);
            const int rr  = r & 15;
            float v[4];
            #pragma unroll
            for (int j = 0; j < 4; ++j) {
                int cc = cc0 + j;
                float x = sm.u.red[q2][rr][cc & 15] + sm.u.red[4 + q2][rr][cc & 15]
                        + bias[cb + cc];
                v[j] = tanhf(x);
            }
            *(float4*)&Hdst[(size_t)(rb + r) * HID + cb + cc0] =
                make_float4(v[0], v[1], v[2], v[3]);
        }

        // grid barrier (skip after the last step)
        if (s < nsteps) {
            __threadfence();                 // release: H writes visible, L1 inval
            __syncthreads();
            if (tid == 0) {
                atomicAdd(&g_cnt, 1u);
                const unsigned target = (unsigned)NBLK * (unsigned)s;
                while (*(volatile unsigned*)&g_cnt < target) { }
                __threadfence();             // acquire: see peers' H writes
            }
            __syncthreads();
        }
    }
}

extern "C" void kernel_launch(void* const* d_in, const int* in_sizes, int n_in,
                              void* d_out, int out_size)
{
    const int*   tokens = (const int*)  d_in[0];   // [511, 256]
    const float* emb    = (const float*)d_in[1];   // [32000, 512]
    const float* Wl     = (const float*)d_in[2];   // [512, 512]
    const float* Wr     = (const float*)d_in[3];   // [512, 512]
    const float* bias   = (const float*)d_in[4];   // [512]
    float* out = (float*)d_out;                    // [256, 512]

    const int T      = in_sizes[0] / BATCH;  // 511
    const int nsteps = (T - 1) / 2;          // 255 reduce steps

    cudaFuncSetAttribute(chain_kernel,
                         cudaFuncAttributeMaxDynamicSharedMemorySize,
                         (int)sizeof(SMem));

    init_kernel<<<BATCH, HID / 4>>>(tokens, emb);
    chain_kernel<<<NBLK, 256, sizeof(SMem)>>>(tokens, emb, Wl, Wr, bias,
                                              out, nsteps);
}

// round 9
// speedup vs baseline: 2.6802x; 1.2605x over previous
#include <cuda_runtime.h>
#include <cuda_bf16.h>
#include <mma.h>
#include <cstddef>

using namespace nvcuda;

#define BATCH 256
#define HID   512
#define NBLK  128           // 8 row-groups x 16 col-tiles, all co-resident
#define WPAD  40            // W smem row stride (elems), mult of 8, LDSM conflict-free
#define APAD  520           // A smem row stride (elems), mult of 8, 1040B = 65 lines
#define RPAD  36            // reduction row stride (fp32)

// ---- scratch (static __device__, allocation-free per harness rules) ----
__device__ __nv_bfloat16 g_Ehi[32000 * HID];   // pre-split embedding, hi plane
__device__ __nv_bfloat16 g_Elo[32000 * HID];   // lo plane
__device__ __nv_bfloat16 g_Hhi[2][BATCH * HID]; // ping-pong hidden state, hi
__device__ __nv_bfloat16 g_Hlo[2][BATCH * HID]; // lo
__device__ unsigned      g_bar[8 * 32];         // per-row-group barrier counters (128B apart)

struct SMem {
    __nv_bfloat16 Whi[1024][WPAD];     // 80KB  block's W column slice, hi plane
    __nv_bfloat16 Wlo[1024][WPAD];     // 80KB  lo plane
    union {
        struct { __nv_bfloat16 hi[32][APAD];
                 __nv_bfloat16 lo[32][APAD]; } a;   // 65KB A phase staging
        float red[8][32][RPAD];                     // 36KB warp-partial reduction
    } u;
    int stok[32];
};

// tokens may be int32 (jax default) or int64. tokens[0][1] is a real token
// >= 3, so a zero second 32-bit word means little-endian int64.
__device__ __forceinline__ int load_tok(const int* tokens, long long idx)
{
    if (tokens[1] == 0) return (int)((const long long*)tokens)[idx];
    return tokens[idx];
}

__device__ __forceinline__ void split_bf16(float x, __nv_bfloat16& hi, __nv_bfloat16& lo)
{
    hi = __float2bfloat16(x);
    lo = __float2bfloat16(x - __bfloat162float(hi));
}

__device__ __forceinline__ void cp_async16(void* dst, const void* src)
{
    unsigned d = (unsigned)__cvta_generic_to_shared(dst);
    asm volatile("cp.async.cg.shared.global [%0], [%1], 16;" :: "r"(d), "l"(src));
}
__device__ __forceinline__ void cp_wait_all()
{
    asm volatile("cp.async.commit_group;\n\tcp.async.wait_group 0;" ::: "memory");
}

// ---- pre-split the embedding table into bf16 hi/lo planes ----
__global__ void prep_emb(const float* __restrict__ emb, int n)
{
    int e = (blockIdx.x * blockDim.x + threadIdx.x) * 4;
    if (e >= n) return;
    float4 v = *(const float4*)(emb + e);
    float xs[4] = {v.x, v.y, v.z, v.w};
    #pragma unroll
    for (int j = 0; j < 4; ++j) {
        __nv_bfloat16 h, l;
        split_bf16(xs[j], h, l);
        g_Ehi[e + j] = h;
        g_Elo[e + j] = l;
    }
}

// ---- h0 = emb[tok0] (already split) ; reset barrier counters ----
__global__ void init_kernel(const int* __restrict__ tokens)
{
    if (blockIdx.x == 0 && threadIdx.x < 8) g_bar[threadIdx.x * 32] = 0u;
    int b = blockIdx.x;
    long long tok = load_tok(tokens, b);
    int c = threadIdx.x * 4;                    // 128 threads x 4 cols
    *(uint2*)&g_Hhi[0][(size_t)b * HID + c] = *(const uint2*)&g_Ehi[tok * HID + c];
    *(uint2*)&g_Hlo[0][(size_t)b * HID + c] = *(const uint2*)&g_Elo[tok * HID + c];
}

// Persistent chain kernel: 255 reduce steps, one launch.
// Block = 32x32 output tile. Each of 8 warps owns a 32x32 warp tile over a
// K=128 slice (two 64-col phases over the fused K=1024 = [H | E]),
// 4 accumulators (16x16 quadrants) for ILP, 3-term bf16-split mma.
// W slice split once into smem. A staged per phase via cp.async.cg from
// pre-split bf16 planes (H planes are produced pre-split by the epilogue).
// Row-groups of 16 blocks are independent chains, separated per step by a
// 16-arrival monotonic-counter barrier.
__global__ void __launch_bounds__(256, 1)
chain_kernel(const int* __restrict__ tokens,
             const float* __restrict__ Wl,
             const float* __restrict__ Wr,
             const float* __restrict__ bias,
             float* __restrict__ out,
             int nsteps)
{
    extern __shared__ char smem_raw[];
    SMem& sm = *reinterpret_cast<SMem*>(smem_raw);

    const int tid = threadIdx.x;
    const int w   = tid >> 5;
    const int rg  = blockIdx.x >> 4;       // row group 0..7
    const int rb  = rg * 32;
    const int cb  = (blockIdx.x & 15) * 32;

    // ---- one-time: load + split this block's W column slice into smem ----
    {
        const int row0 = tid >> 3;
        const int cq   = (tid & 7) * 4;
        for (int it = 0; it < 32; ++it) {
            int row = it * 32 + row0;                  // 0..1023 over [Wl ; Wr]
            const float* src = (row < HID)
                ? (Wl + (size_t)row * HID + cb + cq)
                : (Wr + (size_t)(row - HID) * HID + cb + cq);
            float4 v = *(const float4*)src;
            float xs[4] = {v.x, v.y, v.z, v.w};
            #pragma unroll
            for (int j = 0; j < 4; ++j) {
                __nv_bfloat16 h, l;
                split_bf16(xs[j], h, l);
                sm.Whi[row][cq + j] = h;
                sm.Wlo[row][cq + j] = l;
            }
        }
    }

    // staging role: thread copies row (tid>>3), 64-col segment (tid&7)
    const int srow = tid >> 3;
    const int sseg = (tid & 7) * 64;

    // epilogue role + cached bias
    const int er  = tid >> 3;
    const int ec0 = (tid & 7) * 4;
    const float4 bias4 = *(const float4*)(bias + cb + ec0);

    __syncthreads();

    for (int s = 1; s <= nsteps; ++s) {
        const __nv_bfloat16* Hhi = g_Hhi[(s - 1) & 1];
        const __nv_bfloat16* Hlo = g_Hlo[(s - 1) & 1];

        if (tid < 32)
            sm.stok[tid] = load_tok(tokens, (long long)(2 * s - 1) * BATCH + rb + tid);
        __syncthreads();

        wmma::fragment<wmma::accumulator, 16, 16, 16, float> acc[2][2];
        #pragma unroll
        for (int mi = 0; mi < 2; ++mi)
            #pragma unroll
            for (int ni = 0; ni < 2; ++ni)
                wmma::fill_fragment(acc[mi][ni], 0.0f);

        #pragma unroll
        for (int phase = 0; phase < 2; ++phase) {
            // ---- stage A phase (32 rows x 512 k-cols, hi+lo) via cp.async ----
            const __nv_bfloat16 *srcHi, *srcLo;
            if (phase == 0) {
                size_t o = (size_t)(rb + srow) * HID + sseg;
                srcHi = Hhi + o;  srcLo = Hlo + o;
            } else {
                size_t o = (size_t)sm.stok[srow] * HID + sseg;
                srcHi = g_Ehi + o;  srcLo = g_Elo + o;
            }
            #pragma unroll
            for (int i = 0; i < 8; ++i) {
                cp_async16(&sm.u.a.hi[srow][sseg + i * 8], srcHi + i * 8);
                cp_async16(&sm.u.a.lo[srow][sseg + i * 8], srcLo + i * 8);
            }
            cp_wait_all();
            __syncthreads();

            const int ak = w * 64;               // this warp's A col base
            const int wk = phase * 512 + w * 64; // this warp's W row base
            #pragma unroll
            for (int kk = 0; kk < 4; ++kk) {
                wmma::fragment<wmma::matrix_a, 16, 16, 16, __nv_bfloat16, wmma::row_major> ah[2], al[2];
                wmma::fragment<wmma::matrix_b, 16, 16, 16, __nv_bfloat16, wmma::row_major> bh[2], bl[2];
                #pragma unroll
                for (int mi = 0; mi < 2; ++mi) {
                    wmma::load_matrix_sync(ah[mi], &sm.u.a.hi[mi * 16][ak + kk * 16], APAD);
                    wmma::load_matrix_sync(al[mi], &sm.u.a.lo[mi * 16][ak + kk * 16], APAD);
                }
                #pragma unroll
                for (int ni = 0; ni < 2; ++ni) {
                    wmma::load_matrix_sync(bh[ni], &sm.Whi[wk + kk * 16][ni * 16], WPAD);
                    wmma::load_matrix_sync(bl[ni], &sm.Wlo[wk + kk * 16][ni * 16], WPAD);
                }
                #pragma unroll
                for (int mi = 0; mi < 2; ++mi)
                    #pragma unroll
                    for (int ni = 0; ni < 2; ++ni) {
                        wmma::mma_sync(acc[mi][ni], ah[mi], bh[ni], acc[mi][ni]);
                        wmma::mma_sync(acc[mi][ni], ah[mi], bl[ni], acc[mi][ni]);
                        wmma::mma_sync(acc[mi][ni], al[mi], bh[ni], acc[mi][ni]);
                    }
            }
            __syncthreads();   // all warps done reading A before it is reused
        }

        // ---- reduce 8 warp partials (A region is dead; union reuse) ----
        #pragma unroll
        for (int mi = 0; mi < 2; ++mi)
            #pragma unroll
            for (int ni = 0; ni < 2; ++ni)
                wmma::store_matrix_sync(&sm.u.red[w][mi * 16][ni * 16],
                                        acc[mi][ni], RPAD, wmma::mem_row_major);
        __syncthreads();

        // ---- epilogue: bias + tanh; write bf16 hi/lo planes (or fp32 out) ----
        {
            float4 sum = *(const float4*)&sm.u.red[0][er][ec0];
            #pragma unroll
            for (int p = 1; p < 8; ++p) {
                float4 t = *(const float4*)&sm.u.red[p][er][ec0];
                sum.x += t.x; sum.y += t.y; sum.z += t.z; sum.w += t.w;
            }
            float v0 = tanhf(sum.x + bias4.x);
            float v1 = tanhf(sum.y + bias4.y);
            float v2 = tanhf(sum.z + bias4.z);
            float v3 = tanhf(sum.w + bias4.w);

            size_t o = (size_t)(rb + er) * HID + cb + ec0;
            if (s == nsteps) {
                *(float4*)&out[o] = make_float4(v0, v1, v2, v3);
            } else {
                __nv_bfloat16 h0, l0, h1, l1, h2, l2, h3, l3;
                split_bf16(v0, h0, l0);
                split_bf16(v1, h1, l1);
                split_bf16(v2, h2, l2);
                split_bf16(v3, h3, l3);
                __nv_bfloat162 hi01 = __halves2bfloat162(h0, h1);
                __nv_bfloat162 hi23 = __halves2bfloat162(h2, h3);
                __nv_bfloat162 lo01 = __halves2bfloat162(l0, l1);
                __nv_bfloat162 lo23 = __halves2bfloat162(l2, l3);
                *(uint2*)&g_Hhi[s & 1][o] =
                    make_uint2(*(unsigned*)&hi01, *(unsigned*)&hi23);
                *(uint2*)&g_Hlo[s & 1][o] =
                    make_uint2(*(unsigned*)&lo01, *(unsigned*)&lo23);
            }
        }

        // ---- per-row-group barrier (16 arrivals) ----
        if (s < nsteps) {
            __threadfence();               // release: H plane writes visible
            __syncthreads();
            if (tid == 0) {
                atomicAdd(&g_bar[rg * 32], 1u);
                const unsigned target = 16u * (unsigned)s;
                while (*(volatile unsigned*)&g_bar[rg * 32] < target) { }
                __threadfence();           // acquire: see peers' writes
            }
            __syncthreads();
        }
    }
}

extern "C" void kernel_launch(void* const* d_in, const int* in_sizes, int n_in,
                              void* d_out, int out_size)
{
    const int*   tokens = (const int*)  d_in[0];   // [511, 256]
    const float* emb    = (const float*)d_in[1];   // [32000, 512]
    const float* Wl     = (const float*)d_in[2];   // [512, 512]
    const float* Wr     = (const float*)d_in[3];   // [512, 512]
    const float* bias   = (const float*)d_in[4];   // [512]
    float* out = (float*)d_out;                    // [256, 512]

    const int T      = in_sizes[0] / BATCH;  // 511
    const int nsteps = (T - 1) / 2;          // 255 reduce steps
    const int nemb   = in_sizes[1];          // 32000*512

    cudaFuncSetAttribute(chain_kernel,
                         cudaFuncAttributeMaxDynamicSharedMemorySize,
                         (int)sizeof(SMem));

    prep_emb<<<(nemb / 4 + 255) / 256, 256>>>(emb, nemb);
    init_kernel<<<BATCH, HID / 4>>>(tokens);
    chain_kernel<<<NBLK, 256, sizeof(SMem)>>>(tokens, Wl, Wr, bias, out, nsteps);
}